// round 1
// baseline (speedup 1.0000x reference)
#include <cuda_runtime.h>
#include <math.h>

#define NN   50000
#define NE   320000
#define NR   3
#define IND  768
#define HIDD 256
#define OUTD 64

// ---------------- scratch (device globals; no allocation allowed) ----------------
__device__ float g_h1[NN * HIDD];
__device__ float g_h2[NN * HIDD];
__device__ float g_s[(size_t)NN * NR * HIDD];   // [N, 3*256] aggregated messages
__device__ float g_qi[NN * NR];
__device__ float g_kj[NN * NR];
__device__ float g_aperm[NE];                   // alpha in CSR-permuted order
__device__ int   g_cnt[NN];                     // histogram / cursor
__device__ int   g_off[NN + 1];                 // CSR offsets
__device__ int   g_pack[NE];                    // src | (et<<20), CSR order
__device__ int   g_epos[NE];                    // edge -> CSR position
__device__ float g_wq[NR * HIDD];
__device__ float g_wk[NR * HIDD];
__device__ float g_h3[NN * OUTD];

// ---------------- GEMM: C[M,256] = A[M,K] @ B[K,256] + bias (opt. relu) ----------
__global__ void __launch_bounds__(256, 2)
sgemm_n256(const float* __restrict__ A, const float* __restrict__ B,
           const float* __restrict__ bias, float* __restrict__ C,
           int M, int K, int doRelu)
{
    __shared__ __align__(16) float As[16][132];
    __shared__ __align__(16) float Bs[16][128];
    const int tid = threadIdx.x;
    const int tx = tid & 15, ty = tid >> 4;
    const int bm = blockIdx.x * 128;
    const int bn = blockIdx.y * 128;
    const int N = 256;

    float acc[8][8];
#pragma unroll
    for (int i = 0; i < 8; i++)
#pragma unroll
        for (int j = 0; j < 8; j++) acc[i][j] = 0.f;

    const int arow = tid >> 2;         // 0..63
    const int acol = (tid & 3) << 2;   // 0,4,8,12
    const int brow = tid >> 5;         // 0..7
    const int bcol = (tid & 31) << 2;  // 0..124

    for (int k0 = 0; k0 < K; k0 += 16) {
#pragma unroll
        for (int i = 0; i < 2; i++) {
            int r = arow + i * 64;
            int gr = bm + r; if (gr > M - 1) gr = M - 1;
            float4 v = *(const float4*)(A + (size_t)gr * K + k0 + acol);
            As[acol + 0][r] = v.x; As[acol + 1][r] = v.y;
            As[acol + 2][r] = v.z; As[acol + 3][r] = v.w;
        }
#pragma unroll
        for (int i = 0; i < 2; i++) {
            int r = brow + i * 8;
            *(float4*)&Bs[r][bcol] = *(const float4*)(B + (size_t)(k0 + r) * N + bn + bcol);
        }
        __syncthreads();
#pragma unroll
        for (int k = 0; k < 16; k++) {
            float ra[8], rb[8];
            *(float4*)&ra[0] = *(float4*)&As[k][ty * 4];
            *(float4*)&ra[4] = *(float4*)&As[k][64 + ty * 4];
            *(float4*)&rb[0] = *(float4*)&Bs[k][tx * 4];
            *(float4*)&rb[4] = *(float4*)&Bs[k][64 + tx * 4];
#pragma unroll
            for (int i = 0; i < 8; i++)
#pragma unroll
                for (int j = 0; j < 8; j++)
                    acc[i][j] = fmaf(ra[i], rb[j], acc[i][j]);
        }
        __syncthreads();
    }

    float bv[8];
#pragma unroll
    for (int j = 0; j < 4; j++) {
        bv[j]     = bias[bn + tx * 4 + j];
        bv[4 + j] = bias[bn + 64 + tx * 4 + j];
    }
#pragma unroll
    for (int i = 0; i < 8; i++) {
        int r = (i < 4) ? (bm + ty * 4 + i) : (bm + 64 + ty * 4 + (i - 4));
        if (r >= M) continue;
        float o[8];
#pragma unroll
        for (int j = 0; j < 8; j++) {
            float v = acc[i][j] + bv[j];
            o[j] = doRelu ? fmaxf(v, 0.f) : v;
        }
        *(float4*)(C + (size_t)r * N + bn + tx * 4)      = make_float4(o[0], o[1], o[2], o[3]);
        *(float4*)(C + (size_t)r * N + bn + 64 + tx * 4) = make_float4(o[4], o[5], o[6], o[7]);
    }
}

// ---------------- GEMM: C[M,64] = relu(A[M,K] @ B[K,64] + bias) -------------------
__global__ void __launch_bounds__(256, 2)
sgemm_n64(const float* __restrict__ A, const float* __restrict__ B,
          const float* __restrict__ bias, float* __restrict__ C, int M, int K)
{
    __shared__ __align__(16) float As[16][132];
    __shared__ __align__(16) float Bs[16][64];
    const int tid = threadIdx.x;
    const int tx = tid & 15, ty = tid >> 4;
    const int bm = blockIdx.x * 128;

    float acc[8][4];
#pragma unroll
    for (int i = 0; i < 8; i++)
#pragma unroll
        for (int j = 0; j < 4; j++) acc[i][j] = 0.f;

    const int arow = tid >> 2, acol = (tid & 3) << 2;
    const int bk = tid >> 4, bn4 = (tid & 15) << 2;

    for (int k0 = 0; k0 < K; k0 += 16) {
#pragma unroll
        for (int i = 0; i < 2; i++) {
            int r = arow + i * 64;
            int gr = bm + r; if (gr > M - 1) gr = M - 1;
            float4 v = *(const float4*)(A + (size_t)gr * K + k0 + acol);
            As[acol + 0][r] = v.x; As[acol + 1][r] = v.y;
            As[acol + 2][r] = v.z; As[acol + 3][r] = v.w;
        }
        *(float4*)&Bs[bk][bn4] = *(const float4*)(B + (size_t)(k0 + bk) * 64 + bn4);
        __syncthreads();
#pragma unroll
        for (int k = 0; k < 16; k++) {
            float ra[8], rb[4];
            *(float4*)&ra[0] = *(float4*)&As[k][ty * 4];
            *(float4*)&ra[4] = *(float4*)&As[k][64 + ty * 4];
            *(float4*)&rb[0] = *(float4*)&Bs[k][tx * 4];
#pragma unroll
            for (int i = 0; i < 8; i++)
#pragma unroll
                for (int j = 0; j < 4; j++)
                    acc[i][j] = fmaf(ra[i], rb[j], acc[i][j]);
        }
        __syncthreads();
    }

    float bv[4];
#pragma unroll
    for (int j = 0; j < 4; j++) bv[j] = bias[tx * 4 + j];
#pragma unroll
    for (int i = 0; i < 8; i++) {
        int r = (i < 4) ? (bm + ty * 4 + i) : (bm + 64 + ty * 4 + (i - 4));
        if (r >= M) continue;
        float4 o;
        o.x = fmaxf(acc[i][0] + bv[0], 0.f);
        o.y = fmaxf(acc[i][1] + bv[1], 0.f);
        o.z = fmaxf(acc[i][2] + bv[2], 0.f);
        o.w = fmaxf(acc[i][3] + bv[3], 0.f);
        *(float4*)(C + (size_t)r * 64 + tx * 4) = o;
    }
}

// ---------------- CSR construction ------------------------------------------------
__global__ void hist_kernel(const int* __restrict__ ei, int* __restrict__ cnt)
{
    int e = blockIdx.x * blockDim.x + threadIdx.x;
    if (e < NE) atomicAdd(&cnt[ei[NE + e]], 1);
}

__global__ void scan_kernel(const int* __restrict__ cnt, int* __restrict__ off)
{
    __shared__ int sums[1024];
    const int t = threadIdx.x;
    const int CH = (NN + 1023) / 1024;   // 49
    const int base = t * CH;
    int mysum = 0;
    for (int i = 0; i < CH; i++) {
        int idx = base + i;
        if (idx < NN) mysum += cnt[idx];
    }
    sums[t] = mysum;
    __syncthreads();
    for (int d = 1; d < 1024; d <<= 1) {
        int v = 0;
        if (t >= d) v = sums[t - d];
        __syncthreads();
        sums[t] += v;
        __syncthreads();
    }
    int run = sums[t] - mysum;   // exclusive prefix
    for (int i = 0; i < CH; i++) {
        int idx = base + i;
        if (idx < NN) { off[idx] = run; run += cnt[idx]; }
    }
    if (t == 1023) off[NN] = sums[1023];
}

__global__ void fill_kernel(const int* __restrict__ ei, const int* __restrict__ etp,
                            const int* __restrict__ off, int* __restrict__ cur,
                            int* __restrict__ pack, int* __restrict__ epos)
{
    int e = blockIdx.x * blockDim.x + threadIdx.x;
    if (e >= NE) return;
    int d = ei[NE + e];
    int p = off[d] + atomicAdd(&cur[d], 1);
    pack[p] = ei[e] | (etp[e] << 20);
    epos[e] = p;
}

// ---------------- attention scalar path -------------------------------------------
__global__ void wqwk_kernel(const float* __restrict__ W, const float* __restrict__ q,
                            const float* __restrict__ k,
                            float* __restrict__ wq, float* __restrict__ wk)
{
    __shared__ float qs[HIDD], ks[HIDD];
    int r = blockIdx.x, c = threadIdx.x;
    qs[c] = q[c]; ks[c] = k[c];
    __syncthreads();
    const float* Wrc = W + ((size_t)r * HIDD + c) * HIDD;
    float aq = 0.f, ak = 0.f;
    for (int o = 0; o < HIDD; o++) {
        float w = Wrc[o];
        aq = fmaf(w, qs[o], aq);
        ak = fmaf(w, ks[o], ak);
    }
    wq[r * HIDD + c] = aq;
    wk[r * HIDD + c] = ak;
}

__global__ void qikj_kernel(const float* __restrict__ h, const float* __restrict__ wq,
                            const float* __restrict__ wk,
                            float* __restrict__ qi, float* __restrict__ kj)
{
    int warp = (blockIdx.x * blockDim.x + threadIdx.x) >> 5;
    int lane = threadIdx.x & 31;
    if (warp >= NN) return;
    const float4* hp = (const float4*)(h + (size_t)warp * HIDD + lane * 8);
    float4 h0 = hp[0], h1 = hp[1];
    float dq[NR], dk[NR];
#pragma unroll
    for (int r = 0; r < NR; r++) {
        const float4* qp = (const float4*)(wq + r * HIDD + lane * 8);
        const float4* kp = (const float4*)(wk + r * HIDD + lane * 8);
        float4 q0 = qp[0], q1 = qp[1];
        float4 k0 = kp[0], k1 = kp[1];
        dq[r] = h0.x*q0.x + h0.y*q0.y + h0.z*q0.z + h0.w*q0.w
              + h1.x*q1.x + h1.y*q1.y + h1.z*q1.z + h1.w*q1.w;
        dk[r] = h0.x*k0.x + h0.y*k0.y + h0.z*k0.z + h0.w*k0.w
              + h1.x*k1.x + h1.y*k1.y + h1.z*k1.z + h1.w*k1.w;
    }
#pragma unroll
    for (int d = 16; d; d >>= 1) {
#pragma unroll
        for (int r = 0; r < NR; r++) {
            dq[r] += __shfl_xor_sync(0xffffffffu, dq[r], d);
            dk[r] += __shfl_xor_sync(0xffffffffu, dk[r], d);
        }
    }
    if (lane == 0) {
#pragma unroll
        for (int r = 0; r < NR; r++) {
            qi[warp * NR + r] = dq[r];
            kj[warp * NR + r] = dk[r];
        }
    }
}

__global__ void alpha_kernel(const int* __restrict__ ei, const int* __restrict__ etp,
                             const float* __restrict__ qi, const float* __restrict__ kj,
                             const int* __restrict__ epos, float* __restrict__ aperm)
{
    int e = blockIdx.x * blockDim.x + threadIdx.x;
    if (e >= NE) return;
    int s = ei[e], d = ei[NE + e], t = etp[e];
    float a = qi[d * NR + t] + kj[s * NR + t];
    a = (a > 0.f) ? a : 0.2f * a;   // leaky_relu
    aperm[epos[e]] = a;
}

// ---------------- per-dst softmax + aggregation (warp per node) --------------------
__global__ void aggregate_kernel(const float* __restrict__ h, const float* __restrict__ aperm,
                                 const int* __restrict__ pack, const int* __restrict__ off,
                                 float* __restrict__ s)
{
    int node = (blockIdx.x * blockDim.x + threadIdx.x) >> 5;
    int lane = threadIdx.x & 31;
    if (node >= NN) return;
    int o0 = off[node], o1 = off[node + 1];

    float a0[8], a1[8], a2[8];
#pragma unroll
    for (int j = 0; j < 8; j++) { a0[j] = 0.f; a1[j] = 0.f; a2[j] = 0.f; }

    if (o1 > o0) {
        float m = -3.4e38f;
        for (int p = o0 + lane; p < o1; p += 32) m = fmaxf(m, aperm[p]);
#pragma unroll
        for (int d = 16; d; d >>= 1) m = fmaxf(m, __shfl_xor_sync(0xffffffffu, m, d));
        float ssum = 0.f;
        for (int p = o0 + lane; p < o1; p += 32) ssum += __expf(aperm[p] - m);
#pragma unroll
        for (int d = 16; d; d >>= 1) ssum += __shfl_xor_sync(0xffffffffu, ssum, d);
        float inv = 1.f / (ssum + 1e-16f);

        for (int p = o0; p < o1; p++) {
            float w = __expf(aperm[p] - m) * inv;
            int pk = pack[p];
            int srcn = pk & 0xFFFFF;
            int t = pk >> 20;
            const float4* hp = (const float4*)(h + (size_t)srcn * HIDD + lane * 8);
            float4 v0 = hp[0], v1 = hp[1];
            if (t == 0) {
                a0[0] = fmaf(w, v0.x, a0[0]); a0[1] = fmaf(w, v0.y, a0[1]);
                a0[2] = fmaf(w, v0.z, a0[2]); a0[3] = fmaf(w, v0.w, a0[3]);
                a0[4] = fmaf(w, v1.x, a0[4]); a0[5] = fmaf(w, v1.y, a0[5]);
                a0[6] = fmaf(w, v1.z, a0[6]); a0[7] = fmaf(w, v1.w, a0[7]);
            } else if (t == 1) {
                a1[0] = fmaf(w, v0.x, a1[0]); a1[1] = fmaf(w, v0.y, a1[1]);
                a1[2] = fmaf(w, v0.z, a1[2]); a1[3] = fmaf(w, v0.w, a1[3]);
                a1[4] = fmaf(w, v1.x, a1[4]); a1[5] = fmaf(w, v1.y, a1[5]);
                a1[6] = fmaf(w, v1.z, a1[6]); a1[7] = fmaf(w, v1.w, a1[7]);
            } else {
                a2[0] = fmaf(w, v0.x, a2[0]); a2[1] = fmaf(w, v0.y, a2[1]);
                a2[2] = fmaf(w, v0.z, a2[2]); a2[3] = fmaf(w, v0.w, a2[3]);
                a2[4] = fmaf(w, v1.x, a2[4]); a2[5] = fmaf(w, v1.y, a2[5]);
                a2[6] = fmaf(w, v1.z, a2[6]); a2[7] = fmaf(w, v1.w, a2[7]);
            }
        }
    }
    float* sp = s + (size_t)node * (NR * HIDD) + lane * 8;
    *(float4*)(sp + 0)   = make_float4(a0[0], a0[1], a0[2], a0[3]);
    *(float4*)(sp + 4)   = make_float4(a0[4], a0[5], a0[6], a0[7]);
    *(float4*)(sp + 256) = make_float4(a1[0], a1[1], a1[2], a1[3]);
    *(float4*)(sp + 260) = make_float4(a1[4], a1[5], a1[6], a1[7]);
    *(float4*)(sp + 512) = make_float4(a2[0], a2[1], a2[2], a2[3]);
    *(float4*)(sp + 516) = make_float4(a2[4], a2[5], a2[6], a2[7]);
}

// ---------------- classifier: out[N,2] = h3[N,64] @ w_cls[64,2] + b_cls ------------
__global__ void cls_kernel(const float* __restrict__ h3, const float* __restrict__ w_cls,
                           const float* __restrict__ b_cls, float* __restrict__ out)
{
    int node = (blockIdx.x * blockDim.x + threadIdx.x) >> 5;
    int lane = threadIdx.x & 31;
    if (node >= NN) return;
    float2 v = *(const float2*)(h3 + (size_t)node * OUTD + lane * 2);
    float4 w = *(const float4*)(w_cls + lane * 4);  // rows lane*2, lane*2+1
    float s0 = v.x * w.x + v.y * w.z;
    float s1 = v.x * w.y + v.y * w.w;
#pragma unroll
    for (int d = 16; d; d >>= 1) {
        s0 += __shfl_xor_sync(0xffffffffu, s0, d);
        s1 += __shfl_xor_sync(0xffffffffu, s1, d);
    }
    if (lane == 0) {
        out[node * 2 + 0] = s0 + b_cls[0];
        out[node * 2 + 1] = s1 + b_cls[1];
    }
}

// ---------------- launcher ---------------------------------------------------------
extern "C" void kernel_launch(void* const* d_in, const int* in_sizes, int n_in,
                              void* d_out, int out_size)
{
    const float* x     = (const float*)d_in[0];
    const int*   ei    = (const int*)d_in[1];
    const int*   etp   = (const int*)d_in[2];
    const float* w_in  = (const float*)d_in[3];
    const float* b_in  = (const float*)d_in[4];
    const float* c1w   = (const float*)d_in[5];
    const float* c1q   = (const float*)d_in[6];
    const float* c1k   = (const float*)d_in[7];
    const float* c1b   = (const float*)d_in[8];
    const float* c2w   = (const float*)d_in[9];
    const float* c2q   = (const float*)d_in[10];
    const float* c2k   = (const float*)d_in[11];
    const float* c2b   = (const float*)d_in[12];
    const float* w_out = (const float*)d_in[13];
    const float* b_out = (const float*)d_in[14];
    const float* w_cls = (const float*)d_in[15];
    const float* b_cls = (const float*)d_in[16];
    float* out = (float*)d_out;

    float *h1, *h2, *s, *qi, *kj, *aperm, *wq, *wk, *h3;
    int *cnt, *off, *pack, *epos;
    cudaGetSymbolAddress((void**)&h1, g_h1);
    cudaGetSymbolAddress((void**)&h2, g_h2);
    cudaGetSymbolAddress((void**)&s, g_s);
    cudaGetSymbolAddress((void**)&qi, g_qi);
    cudaGetSymbolAddress((void**)&kj, g_kj);
    cudaGetSymbolAddress((void**)&aperm, g_aperm);
    cudaGetSymbolAddress((void**)&wq, g_wq);
    cudaGetSymbolAddress((void**)&wk, g_wk);
    cudaGetSymbolAddress((void**)&h3, g_h3);
    cudaGetSymbolAddress((void**)&cnt, g_cnt);
    cudaGetSymbolAddress((void**)&off, g_off);
    cudaGetSymbolAddress((void**)&pack, g_pack);
    cudaGetSymbolAddress((void**)&epos, g_epos);

    dim3 gemmGrid((NN + 127) / 128, 2);
    const int EBLK = (NE + 255) / 256;
    const int WBLK = (NN * 32 + 255) / 256;

    // input layer: h1 = relu(x @ w_in + b_in)
    sgemm_n256<<<gemmGrid, 256>>>(x, w_in, b_in, h1, NN, IND, 1);

    // CSR by dst (shared across both convs)
    cudaMemsetAsync(cnt, 0, NN * sizeof(int));
    hist_kernel<<<EBLK, 256>>>(ei, cnt);
    scan_kernel<<<1, 1024>>>(cnt, off);
    cudaMemsetAsync(cnt, 0, NN * sizeof(int));
    fill_kernel<<<EBLK, 256>>>(ei, etp, off, cnt, pack, epos);

    // conv1: h2 = RGAT(h1)
    wqwk_kernel<<<NR, HIDD>>>(c1w, c1q, c1k, wq, wk);
    qikj_kernel<<<WBLK, 256>>>(h1, wq, wk, qi, kj);
    alpha_kernel<<<EBLK, 256>>>(ei, etp, qi, kj, epos, aperm);
    aggregate_kernel<<<WBLK, 256>>>(h1, aperm, pack, off, s);
    sgemm_n256<<<gemmGrid, 256>>>(s, c1w, c1b, h2, NN, NR * HIDD, 0);

    // conv2: h1 = RGAT(h2)
    wqwk_kernel<<<NR, HIDD>>>(c2w, c2q, c2k, wq, wk);
    qikj_kernel<<<WBLK, 256>>>(h2, wq, wk, qi, kj);
    alpha_kernel<<<EBLK, 256>>>(ei, etp, qi, kj, epos, aperm);
    aggregate_kernel<<<WBLK, 256>>>(h2, aperm, pack, off, s);
    sgemm_n256<<<gemmGrid, 256>>>(s, c2w, c2b, h1, NN, NR * HIDD, 0);

    // head: h3 = relu(h1 @ w_out + b_out); out = h3 @ w_cls + b_cls
    sgemm_n64<<<dim3((NN + 127) / 128, 1), 256>>>(h1, w_out, b_out, h3, NN, HIDD);
    cls_kernel<<<WBLK, 256>>>(h3, w_cls, b_cls, out);
}

// round 2
// speedup vs baseline: 1.0239x; 1.0239x over previous
#include <cuda_runtime.h>
#include <math.h>

#define NN   50000
#define NE   320000
#define NR   3
#define IND  768
#define HIDD 256
#define OUTD 64

// ---------------- scratch (device globals; no allocation allowed) ----------------
__device__ float g_h1[NN * HIDD];
__device__ float g_h2[NN * HIDD];
__device__ float g_s[(size_t)NN * NR * HIDD];   // [N, 3*256] aggregated messages
__device__ float g_qi[NN * NR];
__device__ float g_kj[NN * NR];
__device__ float g_aperm[NE];                   // alpha in CSR-permuted order
__device__ int   g_cnt[NN];                     // histogram / cursor
__device__ int   g_off[NN + 1];                 // CSR offsets
__device__ int   g_pack[NE];                    // src | (et<<20), CSR order
__device__ int   g_epos[NE];                    // edge -> CSR position
__device__ float g_wq[NR * HIDD];
__device__ float g_wk[NR * HIDD];
__device__ float g_h3[NN * OUTD];

// ---------------- packed f32x2 helpers (sm_103a FFMA2) -----------------------------
__device__ __forceinline__ void ffma2(unsigned long long& d,
                                      unsigned long long a, unsigned long long b)
{
    asm("fma.rn.f32x2 %0, %1, %2, %0;" : "+l"(d) : "l"(a), "l"(b));
}
__device__ __forceinline__ unsigned long long pack2(float lo, float hi)
{
    unsigned long long r;
    asm("mov.b64 %0, {%1, %2};" : "=l"(r) : "f"(lo), "f"(hi));
    return r;
}
__device__ __forceinline__ float2 unpack2(unsigned long long p)
{
    float2 f;
    asm("mov.b64 {%0, %1}, %2;" : "=f"(f.x), "=f"(f.y) : "l"(p));
    return f;
}

// ---------------- GEMM: C[M,256] = A[M,K] @ B[K,256] + bias (opt. relu) ----------
// 128x128 tile per block, 8x8 per thread, inner product via packed FFMA2.
__global__ void __launch_bounds__(256, 2)
sgemm_n256(const float* __restrict__ A, const float* __restrict__ B,
           const float* __restrict__ bias, float* __restrict__ C,
           int M, int K, int doRelu)
{
    __shared__ __align__(16) float As[16][132];
    __shared__ __align__(16) float Bs[16][128];
    const int tid = threadIdx.x;
    const int tx = tid & 15, ty = tid >> 4;
    const int bm = blockIdx.x * 128;
    const int bn = blockIdx.y * 128;
    const int N = 256;

    // acc2[ip][j]: ip=0..3 row-pairs. ip0:(ty*4+0, ty*4+1), ip1:(ty*4+2, +3),
    // ip2:(64+ty*4+0, +1), ip3:(64+ty*4+2, +3). j = column index within thread.
    unsigned long long acc2[4][8];
#pragma unroll
    for (int i = 0; i < 4; i++)
#pragma unroll
        for (int j = 0; j < 8; j++) acc2[i][j] = 0ull;

    const int arow = tid >> 2;         // 0..63
    const int acol = (tid & 3) << 2;   // 0,4,8,12
    const int brow = tid >> 5;         // 0..7
    const int bcol = (tid & 31) << 2;  // 0..124

    for (int k0 = 0; k0 < K; k0 += 16) {
#pragma unroll
        for (int i = 0; i < 2; i++) {
            int r = arow + i * 64;
            int gr = bm + r; if (gr > M - 1) gr = M - 1;
            float4 v = *(const float4*)(A + (size_t)gr * K + k0 + acol);
            As[acol + 0][r] = v.x; As[acol + 1][r] = v.y;
            As[acol + 2][r] = v.z; As[acol + 3][r] = v.w;
        }
#pragma unroll
        for (int i = 0; i < 2; i++) {
            int r = brow + i * 8;
            *(float4*)&Bs[r][bcol] = *(const float4*)(B + (size_t)(k0 + r) * N + bn + bcol);
        }
        __syncthreads();
#pragma unroll
        for (int k = 0; k < 16; k++) {
            float4 a0 = *(float4*)&As[k][ty * 4];
            float4 a1 = *(float4*)&As[k][64 + ty * 4];
            float4 b0 = *(float4*)&Bs[k][tx * 4];
            float4 b1 = *(float4*)&Bs[k][64 + tx * 4];
            unsigned long long ra2[4], rb2[8];
            ra2[0] = pack2(a0.x, a0.y); ra2[1] = pack2(a0.z, a0.w);
            ra2[2] = pack2(a1.x, a1.y); ra2[3] = pack2(a1.z, a1.w);
            rb2[0] = pack2(b0.x, b0.x); rb2[1] = pack2(b0.y, b0.y);
            rb2[2] = pack2(b0.z, b0.z); rb2[3] = pack2(b0.w, b0.w);
            rb2[4] = pack2(b1.x, b1.x); rb2[5] = pack2(b1.y, b1.y);
            rb2[6] = pack2(b1.z, b1.z); rb2[7] = pack2(b1.w, b1.w);
#pragma unroll
            for (int ip = 0; ip < 4; ip++)
#pragma unroll
                for (int j = 0; j < 8; j++)
                    ffma2(acc2[ip][j], ra2[ip], rb2[j]);
        }
        __syncthreads();
    }

    float bv[8];
#pragma unroll
    for (int j = 0; j < 4; j++) {
        bv[j]     = bias[bn + tx * 4 + j];
        bv[4 + j] = bias[bn + 64 + tx * 4 + j];
    }
#pragma unroll
    for (int ip = 0; ip < 4; ip++) {
        int r_lo = (ip < 2) ? (bm + ty * 4 + 2 * ip) : (bm + 64 + ty * 4 + 2 * (ip - 2));
        float2 u[8];
#pragma unroll
        for (int j = 0; j < 8; j++) u[j] = unpack2(acc2[ip][j]);
#pragma unroll
        for (int half = 0; half < 2; half++) {
            int r = r_lo + half;
            if (r >= M) continue;
            float o[8];
#pragma unroll
            for (int j = 0; j < 8; j++) {
                float v = (half ? u[j].y : u[j].x) + bv[j];
                o[j] = doRelu ? fmaxf(v, 0.f) : v;
            }
            *(float4*)(C + (size_t)r * N + bn + tx * 4)      = make_float4(o[0], o[1], o[2], o[3]);
            *(float4*)(C + (size_t)r * N + bn + 64 + tx * 4) = make_float4(o[4], o[5], o[6], o[7]);
        }
    }
}

// ---------------- GEMM: C[M,64] = relu(A[M,K] @ B[K,64] + bias) -------------------
__global__ void __launch_bounds__(256, 2)
sgemm_n64(const float* __restrict__ A, const float* __restrict__ B,
          const float* __restrict__ bias, float* __restrict__ C, int M, int K)
{
    __shared__ __align__(16) float As[16][132];
    __shared__ __align__(16) float Bs[16][64];
    const int tid = threadIdx.x;
    const int tx = tid & 15, ty = tid >> 4;
    const int bm = blockIdx.x * 128;

    unsigned long long acc2[4][4];
#pragma unroll
    for (int i = 0; i < 4; i++)
#pragma unroll
        for (int j = 0; j < 4; j++) acc2[i][j] = 0ull;

    const int arow = tid >> 2, acol = (tid & 3) << 2;
    const int bk = tid >> 4, bn4 = (tid & 15) << 2;

    for (int k0 = 0; k0 < K; k0 += 16) {
#pragma unroll
        for (int i = 0; i < 2; i++) {
            int r = arow + i * 64;
            int gr = bm + r; if (gr > M - 1) gr = M - 1;
            float4 v = *(const float4*)(A + (size_t)gr * K + k0 + acol);
            As[acol + 0][r] = v.x; As[acol + 1][r] = v.y;
            As[acol + 2][r] = v.z; As[acol + 3][r] = v.w;
        }
        *(float4*)&Bs[bk][bn4] = *(const float4*)(B + (size_t)(k0 + bk) * 64 + bn4);
        __syncthreads();
#pragma unroll
        for (int k = 0; k < 16; k++) {
            float4 a0 = *(float4*)&As[k][ty * 4];
            float4 a1 = *(float4*)&As[k][64 + ty * 4];
            float4 b0 = *(float4*)&Bs[k][tx * 4];
            unsigned long long ra2[4], rb2[4];
            ra2[0] = pack2(a0.x, a0.y); ra2[1] = pack2(a0.z, a0.w);
            ra2[2] = pack2(a1.x, a1.y); ra2[3] = pack2(a1.z, a1.w);
            rb2[0] = pack2(b0.x, b0.x); rb2[1] = pack2(b0.y, b0.y);
            rb2[2] = pack2(b0.z, b0.z); rb2[3] = pack2(b0.w, b0.w);
#pragma unroll
            for (int ip = 0; ip < 4; ip++)
#pragma unroll
                for (int j = 0; j < 4; j++)
                    ffma2(acc2[ip][j], ra2[ip], rb2[j]);
        }
        __syncthreads();
    }

    float bv[4];
#pragma unroll
    for (int j = 0; j < 4; j++) bv[j] = bias[tx * 4 + j];
#pragma unroll
    for (int ip = 0; ip < 4; ip++) {
        int r_lo = (ip < 2) ? (bm + ty * 4 + 2 * ip) : (bm + 64 + ty * 4 + 2 * (ip - 2));
        float2 u[4];
#pragma unroll
        for (int j = 0; j < 4; j++) u[j] = unpack2(acc2[ip][j]);
#pragma unroll
        for (int half = 0; half < 2; half++) {
            int r = r_lo + half;
            if (r >= M) continue;
            float4 o;
            o.x = fmaxf((half ? u[0].y : u[0].x) + bv[0], 0.f);
            o.y = fmaxf((half ? u[1].y : u[1].x) + bv[1], 0.f);
            o.z = fmaxf((half ? u[2].y : u[2].x) + bv[2], 0.f);
            o.w = fmaxf((half ? u[3].y : u[3].x) + bv[3], 0.f);
            *(float4*)(C + (size_t)r * 64 + tx * 4) = o;
        }
    }
}

// ---------------- CSR construction ------------------------------------------------
__global__ void hist_kernel(const int* __restrict__ ei, int* __restrict__ cnt)
{
    int e = blockIdx.x * blockDim.x + threadIdx.x;
    if (e < NE) atomicAdd(&cnt[ei[NE + e]], 1);
}

__global__ void scan_kernel(const int* __restrict__ cnt, int* __restrict__ off)
{
    __shared__ int sums[1024];
    const int t = threadIdx.x;
    const int CH = (NN + 1023) / 1024;   // 49
    const int base = t * CH;
    int mysum = 0;
    for (int i = 0; i < CH; i++) {
        int idx = base + i;
        if (idx < NN) mysum += cnt[idx];
    }
    sums[t] = mysum;
    __syncthreads();
    for (int d = 1; d < 1024; d <<= 1) {
        int v = 0;
        if (t >= d) v = sums[t - d];
        __syncthreads();
        sums[t] += v;
        __syncthreads();
    }
    int run = sums[t] - mysum;   // exclusive prefix
    for (int i = 0; i < CH; i++) {
        int idx = base + i;
        if (idx < NN) { off[idx] = run; run += cnt[idx]; }
    }
    if (t == 1023) off[NN] = sums[1023];
}

__global__ void fill_kernel(const int* __restrict__ ei, const int* __restrict__ etp,
                            const int* __restrict__ off, int* __restrict__ cur,
                            int* __restrict__ pack, int* __restrict__ epos)
{
    int e = blockIdx.x * blockDim.x + threadIdx.x;
    if (e >= NE) return;
    int d = ei[NE + e];
    int p = off[d] + atomicAdd(&cur[d], 1);
    pack[p] = ei[e] | (etp[e] << 20);
    epos[e] = p;
}

// ---------------- attention scalar path -------------------------------------------
__global__ void wqwk_kernel(const float* __restrict__ W, const float* __restrict__ q,
                            const float* __restrict__ k,
                            float* __restrict__ wq, float* __restrict__ wk)
{
    __shared__ float qs[HIDD], ks[HIDD];
    int r = blockIdx.x, c = threadIdx.x;
    qs[c] = q[c]; ks[c] = k[c];
    __syncthreads();
    const float* Wrc = W + ((size_t)r * HIDD + c) * HIDD;
    float aq = 0.f, ak = 0.f;
    for (int o = 0; o < HIDD; o++) {
        float w = Wrc[o];
        aq = fmaf(w, qs[o], aq);
        ak = fmaf(w, ks[o], ak);
    }
    wq[r * HIDD + c] = aq;
    wk[r * HIDD + c] = ak;
}

__global__ void qikj_kernel(const float* __restrict__ h, const float* __restrict__ wq,
                            const float* __restrict__ wk,
                            float* __restrict__ qi, float* __restrict__ kj)
{
    int warp = (blockIdx.x * blockDim.x + threadIdx.x) >> 5;
    int lane = threadIdx.x & 31;
    if (warp >= NN) return;
    const float4* hp = (const float4*)(h + (size_t)warp * HIDD + lane * 8);
    float4 h0 = hp[0], h1 = hp[1];
    float dq[NR], dk[NR];
#pragma unroll
    for (int r = 0; r < NR; r++) {
        const float4* qp = (const float4*)(wq + r * HIDD + lane * 8);
        const float4* kp = (const float4*)(wk + r * HIDD + lane * 8);
        float4 q0 = qp[0], q1 = qp[1];
        float4 k0 = kp[0], k1 = kp[1];
        dq[r] = h0.x*q0.x + h0.y*q0.y + h0.z*q0.z + h0.w*q0.w
              + h1.x*q1.x + h1.y*q1.y + h1.z*q1.z + h1.w*q1.w;
        dk[r] = h0.x*k0.x + h0.y*k0.y + h0.z*k0.z + h0.w*k0.w
              + h1.x*k1.x + h1.y*k1.y + h1.z*k1.z + h1.w*k1.w;
    }
#pragma unroll
    for (int d = 16; d; d >>= 1) {
#pragma unroll
        for (int r = 0; r < NR; r++) {
            dq[r] += __shfl_xor_sync(0xffffffffu, dq[r], d);
            dk[r] += __shfl_xor_sync(0xffffffffu, dk[r], d);
        }
    }
    if (lane == 0) {
#pragma unroll
        for (int r = 0; r < NR; r++) {
            qi[warp * NR + r] = dq[r];
            kj[warp * NR + r] = dk[r];
        }
    }
}

__global__ void alpha_kernel(const int* __restrict__ ei, const int* __restrict__ etp,
                             const float* __restrict__ qi, const float* __restrict__ kj,
                             const int* __restrict__ epos, float* __restrict__ aperm)
{
    int e = blockIdx.x * blockDim.x + threadIdx.x;
    if (e >= NE) return;
    int s = ei[e], d = ei[NE + e], t = etp[e];
    float a = qi[d * NR + t] + kj[s * NR + t];
    a = (a > 0.f) ? a : 0.2f * a;   // leaky_relu
    aperm[epos[e]] = a;
}

// ---------------- per-dst softmax + aggregation (warp per node) --------------------
__global__ void aggregate_kernel(const float* __restrict__ h, const float* __restrict__ aperm,
                                 const int* __restrict__ pack, const int* __restrict__ off,
                                 float* __restrict__ s)
{
    int node = (blockIdx.x * blockDim.x + threadIdx.x) >> 5;
    int lane = threadIdx.x & 31;
    if (node >= NN) return;
    int o0 = off[node], o1 = off[node + 1];

    float a0[8], a1[8], a2[8];
#pragma unroll
    for (int j = 0; j < 8; j++) { a0[j] = 0.f; a1[j] = 0.f; a2[j] = 0.f; }

    if (o1 > o0) {
        float m = -3.4e38f;
        for (int p = o0 + lane; p < o1; p += 32) m = fmaxf(m, aperm[p]);
#pragma unroll
        for (int d = 16; d; d >>= 1) m = fmaxf(m, __shfl_xor_sync(0xffffffffu, m, d));
        float ssum = 0.f;
        for (int p = o0 + lane; p < o1; p += 32) ssum += __expf(aperm[p] - m);
#pragma unroll
        for (int d = 16; d; d >>= 1) ssum += __shfl_xor_sync(0xffffffffu, ssum, d);
        float inv = 1.f / (ssum + 1e-16f);

        for (int p = o0; p < o1; p++) {
            float w = __expf(aperm[p] - m) * inv;
            int pk = pack[p];
            int srcn = pk & 0xFFFFF;
            int t = pk >> 20;
            const float4* hp = (const float4*)(h + (size_t)srcn * HIDD + lane * 8);
            float4 v0 = hp[0], v1 = hp[1];
            if (t == 0) {
                a0[0] = fmaf(w, v0.x, a0[0]); a0[1] = fmaf(w, v0.y, a0[1]);
                a0[2] = fmaf(w, v0.z, a0[2]); a0[3] = fmaf(w, v0.w, a0[3]);
                a0[4] = fmaf(w, v1.x, a0[4]); a0[5] = fmaf(w, v1.y, a0[5]);
                a0[6] = fmaf(w, v1.z, a0[6]); a0[7] = fmaf(w, v1.w, a0[7]);
            } else if (t == 1) {
                a1[0] = fmaf(w, v0.x, a1[0]); a1[1] = fmaf(w, v0.y, a1[1]);
                a1[2] = fmaf(w, v0.z, a1[2]); a1[3] = fmaf(w, v0.w, a1[3]);
                a1[4] = fmaf(w, v1.x, a1[4]); a1[5] = fmaf(w, v1.y, a1[5]);
                a1[6] = fmaf(w, v1.z, a1[6]); a1[7] = fmaf(w, v1.w, a1[7]);
            } else {
                a2[0] = fmaf(w, v0.x, a2[0]); a2[1] = fmaf(w, v0.y, a2[1]);
                a2[2] = fmaf(w, v0.z, a2[2]); a2[3] = fmaf(w, v0.w, a2[3]);
                a2[4] = fmaf(w, v1.x, a2[4]); a2[5] = fmaf(w, v1.y, a2[5]);
                a2[6] = fmaf(w, v1.z, a2[6]); a2[7] = fmaf(w, v1.w, a2[7]);
            }
        }
    }
    float* sp = s + (size_t)node * (NR * HIDD) + lane * 8;
    *(float4*)(sp + 0)   = make_float4(a0[0], a0[1], a0[2], a0[3]);
    *(float4*)(sp + 4)   = make_float4(a0[4], a0[5], a0[6], a0[7]);
    *(float4*)(sp + 256) = make_float4(a1[0], a1[1], a1[2], a1[3]);
    *(float4*)(sp + 260) = make_float4(a1[4], a1[5], a1[6], a1[7]);
    *(float4*)(sp + 512) = make_float4(a2[0], a2[1], a2[2], a2[3]);
    *(float4*)(sp + 516) = make_float4(a2[4], a2[5], a2[6], a2[7]);
}

// ---------------- classifier: out[N,2] = h3[N,64] @ w_cls[64,2] + b_cls ------------
__global__ void cls_kernel(const float* __restrict__ h3, const float* __restrict__ w_cls,
                           const float* __restrict__ b_cls, float* __restrict__ out)
{
    int node = (blockIdx.x * blockDim.x + threadIdx.x) >> 5;
    int lane = threadIdx.x & 31;
    if (node >= NN) return;
    float2 v = *(const float2*)(h3 + (size_t)node * OUTD + lane * 2);
    float4 w = *(const float4*)(w_cls + lane * 4);  // rows lane*2, lane*2+1
    float s0 = v.x * w.x + v.y * w.z;
    float s1 = v.x * w.y + v.y * w.w;
#pragma unroll
    for (int d = 16; d; d >>= 1) {
        s0 += __shfl_xor_sync(0xffffffffu, s0, d);
        s1 += __shfl_xor_sync(0xffffffffu, s1, d);
    }
    if (lane == 0) {
        out[node * 2 + 0] = s0 + b_cls[0];
        out[node * 2 + 1] = s1 + b_cls[1];
    }
}

// ---------------- launcher ---------------------------------------------------------
extern "C" void kernel_launch(void* const* d_in, const int* in_sizes, int n_in,
                              void* d_out, int out_size)
{
    const float* x     = (const float*)d_in[0];
    const int*   ei    = (const int*)d_in[1];
    const int*   etp   = (const int*)d_in[2];
    const float* w_in  = (const float*)d_in[3];
    const float* b_in  = (const float*)d_in[4];
    const float* c1w   = (const float*)d_in[5];
    const float* c1q   = (const float*)d_in[6];
    const float* c1k   = (const float*)d_in[7];
    const float* c1b   = (const float*)d_in[8];
    const float* c2w   = (const float*)d_in[9];
    const float* c2q   = (const float*)d_in[10];
    const float* c2k   = (const float*)d_in[11];
    const float* c2b   = (const float*)d_in[12];
    const float* w_out = (const float*)d_in[13];
    const float* b_out = (const float*)d_in[14];
    const float* w_cls = (const float*)d_in[15];
    const float* b_cls = (const float*)d_in[16];
    float* out = (float*)d_out;

    float *h1, *h2, *s, *qi, *kj, *aperm, *wq, *wk, *h3;
    int *cnt, *off, *pack, *epos;
    cudaGetSymbolAddress((void**)&h1, g_h1);
    cudaGetSymbolAddress((void**)&h2, g_h2);
    cudaGetSymbolAddress((void**)&s, g_s);
    cudaGetSymbolAddress((void**)&qi, g_qi);
    cudaGetSymbolAddress((void**)&kj, g_kj);
    cudaGetSymbolAddress((void**)&aperm, g_aperm);
    cudaGetSymbolAddress((void**)&wq, g_wq);
    cudaGetSymbolAddress((void**)&wk, g_wk);
    cudaGetSymbolAddress((void**)&h3, g_h3);
    cudaGetSymbolAddress((void**)&cnt, g_cnt);
    cudaGetSymbolAddress((void**)&off, g_off);
    cudaGetSymbolAddress((void**)&pack, g_pack);
    cudaGetSymbolAddress((void**)&epos, g_epos);

    dim3 gemmGrid((NN + 127) / 128, 2);
    const int EBLK = (NE + 255) / 256;
    const int WBLK = (NN * 32 + 255) / 256;

    // input layer: h1 = relu(x @ w_in + b_in)
    sgemm_n256<<<gemmGrid, 256>>>(x, w_in, b_in, h1, NN, IND, 1);

    // CSR by dst (shared across both convs)
    cudaMemsetAsync(cnt, 0, NN * sizeof(int));
    hist_kernel<<<EBLK, 256>>>(ei, cnt);
    scan_kernel<<<1, 1024>>>(cnt, off);
    cudaMemsetAsync(cnt, 0, NN * sizeof(int));
    fill_kernel<<<EBLK, 256>>>(ei, etp, off, cnt, pack, epos);

    // conv1: h2 = RGAT(h1)
    wqwk_kernel<<<NR, HIDD>>>(c1w, c1q, c1k, wq, wk);
    qikj_kernel<<<WBLK, 256>>>(h1, wq, wk, qi, kj);
    alpha_kernel<<<EBLK, 256>>>(ei, etp, qi, kj, epos, aperm);
    aggregate_kernel<<<WBLK, 256>>>(h1, aperm, pack, off, s);
    sgemm_n256<<<gemmGrid, 256>>>(s, c1w, c1b, h2, NN, NR * HIDD, 0);

    // conv2: h1 = RGAT(h2)
    wqwk_kernel<<<NR, HIDD>>>(c2w, c2q, c2k, wq, wk);
    qikj_kernel<<<WBLK, 256>>>(h2, wq, wk, qi, kj);
    alpha_kernel<<<EBLK, 256>>>(ei, etp, qi, kj, epos, aperm);
    aggregate_kernel<<<WBLK, 256>>>(h2, aperm, pack, off, s);
    sgemm_n256<<<gemmGrid, 256>>>(s, c2w, c2b, h1, NN, NR * HIDD, 0);

    // head: h3 = relu(h1 @ w_out + b_out); out = h3 @ w_cls + b_cls
    sgemm_n64<<<dim3((NN + 127) / 128, 1), 256>>>(h1, w_out, b_out, h3, NN, HIDD);
    cls_kernel<<<WBLK, 256>>>(h3, w_cls, b_cls, out);
}